// round 14
// baseline (speedup 1.0000x reference)
#include <cuda_runtime.h>
#include <cuda_fp16.h>
#include <math.h>
#include <stdint.h>

#define EMB 512
#define NHEAD 8
#define DHEAD 64
#define SEQ 4096
#define BATCH 2
#define WINDOW 128
#define MTOT (BATCH * SEQ)   // 8192

// fp16 operands ([token][EMB] layout)
__device__ __half g_xh[(size_t)MTOT * EMB];
__device__ __half g_qh[(size_t)MTOT * EMB];   // pre-scaled by log2(e)/sqrt(512)
__device__ __half g_kh[(size_t)MTOT * EMB];
__device__ __half g_vh[(size_t)MTOT * EMB];
__device__ __half g_oh[(size_t)MTOT * EMB];
__device__ __half g_w[4][EMB * EMB];          // fp16 weights

// ---------------------------------------------------------------------------
// helpers (base sm_103 ISA: cp.async + ldmatrix + mma.sync)
// ---------------------------------------------------------------------------
static __device__ __forceinline__ uint32_t smem_u32(const void* p) {
    uint32_t a;
    asm("{ .reg .u64 t; cvta.to.shared.u64 t, %1; cvt.u32.u64 %0, t; }"
        : "=r"(a) : "l"(p));
    return a;
}
static __device__ __forceinline__ void cp16(uint32_t dst, const void* src) {
    asm volatile("cp.async.cg.shared.global [%0], [%1], 16;" :: "r"(dst), "l"(src));
}
#define CP_COMMIT() asm volatile("cp.async.commit_group;" ::: "memory")
#define CP_WAIT(n)  asm volatile("cp.async.wait_group %0;" :: "n"(n) : "memory")

static __device__ __forceinline__ void ldm_x4(uint32_t& r0, uint32_t& r1,
                                              uint32_t& r2, uint32_t& r3, uint32_t a) {
    asm volatile("ldmatrix.sync.aligned.m8n8.x4.shared.b16 {%0,%1,%2,%3}, [%4];"
                 : "=r"(r0), "=r"(r1), "=r"(r2), "=r"(r3) : "r"(a));
}
static __device__ __forceinline__ void ldm_x4_t(uint32_t& r0, uint32_t& r1,
                                                uint32_t& r2, uint32_t& r3, uint32_t a) {
    asm volatile("ldmatrix.sync.aligned.m8n8.x4.trans.shared.b16 {%0,%1,%2,%3}, [%4];"
                 : "=r"(r0), "=r"(r1), "=r"(r2), "=r"(r3) : "r"(a));
}
static __device__ __forceinline__ void mma_f16(float* d, const uint32_t* a, const uint32_t* b) {
    asm volatile(
        "mma.sync.aligned.m16n8k16.row.col.f32.f16.f16.f32 "
        "{%0,%1,%2,%3}, {%4,%5,%6,%7}, {%8,%9}, {%0,%1,%2,%3};"
        : "+f"(d[0]), "+f"(d[1]), "+f"(d[2]), "+f"(d[3])
        : "r"(a[0]), "r"(a[1]), "r"(a[2]), "r"(a[3]), "r"(b[0]), "r"(b[1]));
}
static __device__ __forceinline__ uint32_t f2h2(float a, float b) {
    __half2 t = __floats2half2_rn(a, b);   // low = a, high = b
    return *(uint32_t*)&t;
}
static __device__ __forceinline__ float ex2f(float x) {
    float y;
    asm("ex2.approx.ftz.f32 %0, %1;" : "=f"(y) : "f"(x));
    return y;
}

// Q prescale: log2(e) / sqrt(512)
#define QSCALE 0.063758715849976f

// ---------------------------------------------------------------------------
// merged conversion: region 0 = x, regions 1..4 = W[0..3]; 2 units/thread (ILP)
// ---------------------------------------------------------------------------
#define XN4 (MTOT * EMB / 4)     // 1048576
#define WN4 (EMB * EMB / 4)      // 65536
#define CONV_TOT (XN4 + 4 * WN4) // 1310720
#define CONV_HALF (CONV_TOT / 2) // 655360

static __device__ __forceinline__ void conv_one(
    int i, const float* __restrict__ x,
    const float* __restrict__ w0, const float* __restrict__ w1,
    const float* __restrict__ w2, const float* __restrict__ w3)
{
    const float* src;
    __half* dst;
    int idx;
    if (i < XN4) {
        src = x; dst = g_xh; idx = i;
    } else {
        int r = (i - XN4) >> 16;          // WN4 = 65536
        idx = (i - XN4) & 65535;
        const float* srcs[4] = {w0, w1, w2, w3};
        src = srcs[r]; dst = g_w[r];
    }
    float4 v = ((const float4*)src)[idx];
    uint2 o;
    o.x = f2h2(v.x, v.y);
    o.y = f2h2(v.z, v.w);
    ((uint2*)dst)[idx] = o;
}

__global__ __launch_bounds__(256) void conv_all(
    const float* __restrict__ x,
    const float* __restrict__ w0, const float* __restrict__ w1,
    const float* __restrict__ w2, const float* __restrict__ w3)
{
    int i = blockIdx.x * blockDim.x + threadIdx.x;
    if (i >= CONV_HALF) return;
    conv_one(i, x, w0, w1, w2, w3);
    conv_one(i + CONV_HALF, x, w0, w1, w2, w3);
}

// ---------------------------------------------------------------------------
// HMMA GEMM: C[m,n] = sum_k A[m,k]*W[n,k] + bias[n],  M=8192, N=K=512
// Single-pass fp16, fp32 accum. 128x128 tile, K-chunk 64, 3-stage cp.async
// pipeline (2 chunks in flight, ONE barrier per chunk), 8 warps (2Mx4N),
// 2 CTAs/SM. QKV fused: grid (64,4,3); final: fin=1.
// Q output (z==0) pre-scaled by log2(e)/sqrt(512).
// ---------------------------------------------------------------------------
#define TILE_BYTES 16384             // 128 rows x 128B
#define STAGE_BYTES (2 * TILE_BYTES) // A, W
#define GEMM_SMEM (3 * STAGE_BYTES)  // 96 KB (3 stages)

static __device__ __forceinline__ void load_stage(
    uint32_t sbase, int buf, int k0, int tid,
    const __half* tA, const __half* tW)
{
    uint32_t stb = sbase + (uint32_t)buf * STAGE_BYTES;
    const __half* t01[2] = {tA, tW};
#pragma unroll
    for (int i = 0; i < 8; i++) {
        int t = i >> 2;
        int idx = tid + (i & 3) * 256;
        int rr = (idx >> 3) & 127;
        int cc = idx & 7;
        uint32_t dst = stb + t * TILE_BYTES + rr * 128 + ((cc ^ (rr & 7)) * 16);
        cp16(dst, t01[t] + (size_t)rr * EMB + k0 + cc * 8);
    }
    CP_COMMIT();
}

__global__ __launch_bounds__(256, 2) void gemm_mma(
    const float* __restrict__ b0, const float* __restrict__ b1,
    const float* __restrict__ b2, float* __restrict__ Cext, int fin)
{
    extern __shared__ __align__(1024) char dsm[];
    const uint32_t sbase = smem_u32(dsm);

    const int z = blockIdx.z;
    const float* bias = fin ? b0 : (z == 0 ? b0 : (z == 1 ? b1 : b2));
    const __half* Aa = fin ? g_oh : g_xh;
    const __half* Bw = g_w[fin ? 3 : z];
    const float oscale = (!fin && z == 0) ? QSCALE : 1.0f;

    const int tid = threadIdx.x;
    const int lane = tid & 31;
    const int wid = tid >> 5;
    const int warp_m = wid >> 2;
    const int warp_n = wid & 3;
    const int bm = blockIdx.x * 128;
    const int bn = blockIdx.y * 128;

    const int lr = lane & 15;
    const int lh = lane >> 4;
    const int l7 = lane & 7;

    float acc[4][4][4];
#pragma unroll
    for (int mt = 0; mt < 4; mt++)
#pragma unroll
        for (int nt = 0; nt < 4; nt++)
#pragma unroll
            for (int j = 0; j < 4; j++) acc[mt][nt][j] = 0.f;

    const __half* tA = Aa + (size_t)bm * EMB;
    const __half* tB = Bw + (size_t)bn * EMB;

    // 3-stage prologue: chunks 0 and 1 in flight
    load_stage(sbase, 0, 0, tid, tA, tB);
    load_stage(sbase, 1, 64, tid, tA, tB);

    const uint32_t arow_off = (uint32_t)(warp_m * 64 + lr) * 128;
    const uint32_t brow_off = (uint32_t)(warp_n * 32 + lr) * 128;

    for (int c = 0; c < 8; ++c) {
        if (c == 7) { CP_WAIT(0); } else { CP_WAIT(1); }
        __syncthreads();                     // single barrier per chunk
        if (c + 2 < 8)
            load_stage(sbase, (c + 2) % 3, (c + 2) * 64, tid, tA, tB);

        const uint32_t sA = sbase + (uint32_t)(c % 3) * STAGE_BYTES;
        const uint32_t sB = sA + TILE_BYTES;

#pragma unroll
        for (int kk = 0; kk < 4; kk++) {
            const uint32_t ch = (uint32_t)(((kk * 2) | lh) ^ l7) * 16;
            uint32_t ah[4][4], bh[4][2];
#pragma unroll
            for (int mt = 0; mt < 4; mt++) {
                uint32_t off = arow_off + (uint32_t)(mt * 16) * 128 + ch;
                ldm_x4(ah[mt][0], ah[mt][1], ah[mt][2], ah[mt][3], sA + off);
            }
#pragma unroll
            for (int p = 0; p < 2; p++) {
                uint32_t off = brow_off + (uint32_t)(p * 16) * 128 + ch;
                uint32_t r0, r1, r2, r3;
                ldm_x4(r0, r1, r2, r3, sB + off);
                bh[p * 2][0] = r0; bh[p * 2][1] = r2;
                bh[p * 2 + 1][0] = r1; bh[p * 2 + 1][1] = r3;
            }
#pragma unroll
            for (int mt = 0; mt < 4; mt++)
#pragma unroll
                for (int nt = 0; nt < 4; nt++)
                    mma_f16(acc[mt][nt], ah[mt], bh[nt]);
        }
    }

    // ---- epilogue ----
    const int g = lane >> 2;
    const int tg = lane & 3;
#pragma unroll
    for (int mt = 0; mt < 4; mt++) {
        int row = bm + warp_m * 64 + mt * 16 + g;
#pragma unroll
        for (int nt = 0; nt < 4; nt++) {
            int col = bn + warp_n * 32 + nt * 8 + tg * 2;
            float bx = bias[col], by = bias[col + 1];
            float v00 = (acc[mt][nt][0] + bx) * oscale, v01 = (acc[mt][nt][1] + by) * oscale;
            float v10 = (acc[mt][nt][2] + bx) * oscale, v11 = (acc[mt][nt][3] + by) * oscale;
            if (fin) {
                float2 a0 = {v00, v01}, a1 = {v10, v11};
                *(float2*)&Cext[(size_t)row * EMB + col] = a0;
                *(float2*)&Cext[(size_t)(row + 8) * EMB + col] = a1;
            } else {
                __half* dst = (z == 0) ? g_qh : ((z == 1) ? g_kh : g_vh);
                *(uint32_t*)&dst[(size_t)row * EMB + col] = f2h2(v00, v01);
                *(uint32_t*)&dst[(size_t)(row + 8) * EMB + col] = f2h2(v10, v11);
            }
        }
    }
}

// ---------------------------------------------------------------------------
// HMMA banded flash attention, no-max softmax, 3-stage K/V pipeline.
// One CTA per (b, h, 64-query tile), 4 warps; warp w owns queries q0+16w..+15.
// Log2-domain (Q pre-scaled by log2e/sqrt(512)). V via ldmatrix.trans.
// l is purely additive -> single shfl reduction after the chunk loop.
// Boundary chunks (kc == q0±128): fully-masked 16-key groups skipped.
// smem 48KB: 3 x (K 8KB + V 8KB) stages.
// ---------------------------------------------------------------------------
__global__ __launch_bounds__(128) void attn_mma()
{
    __shared__ __align__(1024) char smem_buf[49152];
    const uint32_t sb0 = smem_u32(smem_buf);

    const int tid = threadIdx.x;
    const int lane = tid & 31;
    const int wid = tid >> 5;
    const int q0 = blockIdx.x * 64;
    const int h = blockIdx.y;
    const int b = blockIdx.z;

    const int lr = lane & 15;
    const int lh = lane >> 4;
    const int l7 = lane & 7;
    const int g = lane >> 2;
    const int tg = lane & 3;

    const size_t tok0 = (size_t)b * SEQ;
    const int colh = h * DHEAD;

    // ---- stage Q (pre-scaled) into stage-0 K-region, extract fragments ----
#pragma unroll
    for (int i = 0; i < 4; i++) {
        int idx = tid + i * 128;
        int rr = idx >> 3, cc = idx & 7;
        cp16(sb0 + rr * 128 + ((cc ^ (rr & 7)) * 16),
             g_qh + (tok0 + q0 + rr) * EMB + colh + cc * 8);
    }
    CP_COMMIT(); CP_WAIT(0); __syncthreads();

    uint32_t qh[4][4];
#pragma unroll
    for (int kk = 0; kk < 4; kk++) {
        uint32_t ch = (uint32_t)(((kk * 2) | lh) ^ l7) * 16;
        uint32_t off = (uint32_t)(wid * 16 + lr) * 128 + ch;
        ldm_x4(qh[kk][0], qh[kk][1], qh[kk][2], qh[kk][3], sb0 + off);
    }
    __syncthreads();

    float oacc[8][4];
#pragma unroll
    for (int j = 0; j < 8; j++)
#pragma unroll
        for (int c = 0; c < 4; c++) oacc[j][c] = 0.f;

    float l0 = 0.f, l8 = 0.f;

    const int qg0 = q0 + wid * 16 + g;
    const int qg8 = qg0 + 8;

    int klo_ = q0 - WINDOW; if (klo_ < 0) klo_ = 0;
    int khi_ = q0 + 64 + WINDOW; if (khi_ > SEQ) khi_ = SEQ;
    const int nch = (khi_ - klo_) >> 6;     // always >= 3

    auto load_kv = [&](int buf, int kc) {
        uint32_t base = sb0 + (uint32_t)buf * 16384;
#pragma unroll
        for (int i = 0; i < 4; i++) {
            int idx = tid + i * 128;
            int rr = idx >> 3, cc = idx & 7;
            uint32_t so = rr * 128 + ((cc ^ (rr & 7)) * 16);
            cp16(base + so, g_kh + (tok0 + kc + rr) * EMB + colh + cc * 8);
            cp16(base + 8192 + so, g_vh + (tok0 + kc + rr) * EMB + colh + cc * 8);
        }
        CP_COMMIT();
    };

    // 3-stage prologue: chunks 0 and 1 in flight
    load_kv(0, klo_);
    load_kv(1, klo_ + 64);

    for (int c = 0; c < nch; c++) {
        const int kc = klo_ + c * 64;
        const int typ = (kc == q0 - 128) ? 1 : ((kc == q0 + 128) ? 2 : 0);
        const int plo = (typ == 1) ? wid : 0;
        const int phi = (typ == 2) ? wid : 3;

        if (c == nch - 1) { CP_WAIT(0); } else { CP_WAIT(1); }
        __syncthreads();
        if (c + 2 < nch) load_kv((c + 2) % 3, kc + 128);

        const uint32_t bK = sb0 + (uint32_t)(c % 3) * 16384;
        const uint32_t bV = bK + 8192;

        // ---- S = Q K^T (log2-domain; skip fully-masked key groups) ----
        float sacc[8][4];
#pragma unroll
        for (int j = 0; j < 8; j++)
#pragma unroll
            for (int cc = 0; cc < 4; cc++) sacc[j][cc] = -1e30f;

#pragma unroll
        for (int p = 0; p < 4; p++) {
            if (p < plo || p > phi) continue;    // warp-uniform skip
#pragma unroll
            for (int j = 0; j < 2; j++)
#pragma unroll
                for (int cc = 0; cc < 4; cc++) sacc[p * 2 + j][cc] = 0.f;
#pragma unroll
            for (int kk = 0; kk < 4; kk++) {
                uint32_t ch = (uint32_t)(((kk * 2) | lh) ^ l7) * 16;
                uint32_t off = (uint32_t)(p * 16 + lr) * 128 + ch;
                uint32_t r0, r1, r2, r3;
                ldm_x4(r0, r1, r2, r3, bK + off);
                uint32_t b0[2] = {r0, r2}, b1[2] = {r1, r3};
                mma_f16(sacc[p * 2], qh[kk], b0);
                mma_f16(sacc[p * 2 + 1], qh[kk], b1);
            }
        }

        // ---- mask (boundary chunks only) ----
        if (typ) {
#pragma unroll
            for (int j = 0; j < 8; j++) {
                int kg = kc + j * 8 + tg * 2;
                if (abs(qg0 - kg) > WINDOW)       sacc[j][0] = -1e30f;
                if (abs(qg0 - (kg + 1)) > WINDOW) sacc[j][1] = -1e30f;
                if (abs(qg8 - kg) > WINDOW)       sacc[j][2] = -1e30f;
                if (abs(qg8 - (kg + 1)) > WINDOW) sacc[j][3] = -1e30f;
            }
        }

        // ---- exp2 (no max subtraction: logits bounded), pack, accumulate l ----
        uint32_t phg[8], phg8[8];
#pragma unroll
        for (int j = 0; j < 8; j++) {
            float p0 = ex2f(sacc[j][0]);
            float p1 = ex2f(sacc[j][1]);
            float p2 = ex2f(sacc[j][2]);
            float p3 = ex2f(sacc[j][3]);
            l0 += p0 + p1; l8 += p2 + p3;
            phg[j]  = f2h2(p0, p1);
            phg8[j] = f2h2(p2, p3);
        }

        // ---- O += P V (skip all-zero P key groups) ----
#pragma unroll
        for (int t = 0; t < 4; t++) {
            if (t < plo || t > phi) continue;    // warp-uniform skip
            uint32_t vh[8][2];
            int row = t * 16 + lr;               // key row for this lane
            uint32_t rbase = bV + (uint32_t)row * 128;
            uint32_t rsw = (uint32_t)(row & 7);
#pragma unroll
            for (int pp = 0; pp < 4; pp++) {
                uint32_t d = (uint32_t)(pp * 2) + (uint32_t)lh;  // dim group (16B)
                uint32_t addr = rbase + ((d ^ rsw) * 16);
                uint32_t r0, r1, r2, r3;
                ldm_x4_t(r0, r1, r2, r3, addr);
                vh[pp * 2][0] = r0;     vh[pp * 2][1] = r1;
                vh[pp * 2 + 1][0] = r2; vh[pp * 2 + 1][1] = r3;
            }
            uint32_t pa_h[4] = {phg[2 * t], phg8[2 * t], phg[2 * t + 1], phg8[2 * t + 1]};
#pragma unroll
            for (int j = 0; j < 8; j++)
                mma_f16(oacc[j], pa_h, vh[j]);
        }
    }

    // ---- single deferred l reduction across the 4 lanes of each row ----
    l0 += __shfl_xor_sync(0xffffffffu, l0, 1);
    l0 += __shfl_xor_sync(0xffffffffu, l0, 2);
    l8 += __shfl_xor_sync(0xffffffffu, l8, 1);
    l8 += __shfl_xor_sync(0xffffffffu, l8, 2);

    // ---- epilogue: normalize, store plain fp16 ----
    float il0 = 1.f / l0, il8 = 1.f / l8;
    size_t r0base = (tok0 + qg0) * EMB + colh;
    size_t r8base = (tok0 + qg8) * EMB + colh;
#pragma unroll
    for (int j = 0; j < 8; j++) {
        int col = j * 8 + tg * 2;
        *(uint32_t*)&g_oh[r0base + col] = f2h2(oacc[j][0] * il0, oacc[j][1] * il0);
        *(uint32_t*)&g_oh[r8base + col] = f2h2(oacc[j][2] * il8, oacc[j][3] * il8);
    }
}

// ---------------------------------------------------------------------------
extern "C" void kernel_launch(void* const* d_in, const int* in_sizes, int n_in,
                              void* d_out, int out_size)
{
    const float* x  = (const float*)d_in[0];
    const float* Wq = (const float*)d_in[1];
    const float* bq = (const float*)d_in[2];
    const float* Wk = (const float*)d_in[3];
    const float* bk = (const float*)d_in[4];
    const float* Wv = (const float*)d_in[5];
    const float* bv = (const float*)d_in[6];
    const float* Wo = (const float*)d_in[7];
    const float* bo = (const float*)d_in[8];
    float* out = (float*)d_out;

    cudaFuncSetAttribute(gemm_mma, cudaFuncAttributeMaxDynamicSharedMemorySize, GEMM_SMEM);

    conv_all<<<(CONV_HALF + 255) / 256, 256>>>(x, Wq, Wk, Wv, Wo);

    gemm_mma<<<dim3(MTOT / 128, EMB / 128, 3), 256, GEMM_SMEM>>>(bq, bk, bv, nullptr, 0);

    attn_mma<<<dim3(SEQ / 64, NHEAD, BATCH), 128>>>();

    gemm_mma<<<dim3(MTOT / 128, EMB / 128, 1), 256, GEMM_SMEM>>>(bo, nullptr, nullptr, out, 1);
}

// round 15
// speedup vs baseline: 1.0691x; 1.0691x over previous
#include <cuda_runtime.h>
#include <cuda_fp16.h>
#include <math.h>
#include <stdint.h>

#define EMB 512
#define NHEAD 8
#define DHEAD 64
#define SEQ 4096
#define BATCH 2
#define WINDOW 128
#define MTOT (BATCH * SEQ)   // 8192

// fp16 operands ([token][EMB] layout)
__device__ __half g_xh[(size_t)MTOT * EMB];
__device__ __half g_qh[(size_t)MTOT * EMB];   // pre-scaled by log2(e)/sqrt(512)
__device__ __half g_kh[(size_t)MTOT * EMB];
__device__ __half g_vh[(size_t)MTOT * EMB];
__device__ __half g_oh[(size_t)MTOT * EMB];
__device__ __half g_w[4][EMB * EMB];          // fp16 weights

// ---------------------------------------------------------------------------
// helpers (base sm_103 ISA: cp.async + ldmatrix + mma.sync)
// ---------------------------------------------------------------------------
static __device__ __forceinline__ uint32_t smem_u32(const void* p) {
    uint32_t a;
    asm("{ .reg .u64 t; cvta.to.shared.u64 t, %1; cvt.u32.u64 %0, t; }"
        : "=r"(a) : "l"(p));
    return a;
}
static __device__ __forceinline__ void cp16(uint32_t dst, const void* src) {
    asm volatile("cp.async.cg.shared.global [%0], [%1], 16;" :: "r"(dst), "l"(src));
}
#define CP_COMMIT() asm volatile("cp.async.commit_group;" ::: "memory")
#define CP_WAIT(n)  asm volatile("cp.async.wait_group %0;" :: "n"(n) : "memory")

static __device__ __forceinline__ void ldm_x4(uint32_t& r0, uint32_t& r1,
                                              uint32_t& r2, uint32_t& r3, uint32_t a) {
    asm volatile("ldmatrix.sync.aligned.m8n8.x4.shared.b16 {%0,%1,%2,%3}, [%4];"
                 : "=r"(r0), "=r"(r1), "=r"(r2), "=r"(r3) : "r"(a));
}
static __device__ __forceinline__ void ldm_x4_t(uint32_t& r0, uint32_t& r1,
                                                uint32_t& r2, uint32_t& r3, uint32_t a) {
    asm volatile("ldmatrix.sync.aligned.m8n8.x4.trans.shared.b16 {%0,%1,%2,%3}, [%4];"
                 : "=r"(r0), "=r"(r1), "=r"(r2), "=r"(r3) : "r"(a));
}
static __device__ __forceinline__ void mma_f16(float* d, const uint32_t* a, const uint32_t* b) {
    asm volatile(
        "mma.sync.aligned.m16n8k16.row.col.f32.f16.f16.f32 "
        "{%0,%1,%2,%3}, {%4,%5,%6,%7}, {%8,%9}, {%0,%1,%2,%3};"
        : "+f"(d[0]), "+f"(d[1]), "+f"(d[2]), "+f"(d[3])
        : "r"(a[0]), "r"(a[1]), "r"(a[2]), "r"(a[3]), "r"(b[0]), "r"(b[1]));
}
static __device__ __forceinline__ uint32_t f2h2(float a, float b) {
    __half2 t = __floats2half2_rn(a, b);   // low = a, high = b
    return *(uint32_t*)&t;
}
static __device__ __forceinline__ float ex2f(float x) {
    float y;
    asm("ex2.approx.ftz.f32 %0, %1;" : "=f"(y) : "f"(x));
    return y;
}

// Q prescale: log2(e) / sqrt(512)
#define QSCALE 0.063758715849976f

// ---------------------------------------------------------------------------
// merged conversion: region 0 = x, regions 1..4 = W[0..3]; 2 units/thread (ILP)
// ---------------------------------------------------------------------------
#define XN4 (MTOT * EMB / 4)     // 1048576
#define WN4 (EMB * EMB / 4)      // 65536
#define CONV_TOT (XN4 + 4 * WN4) // 1310720
#define CONV_HALF (CONV_TOT / 2) // 655360

static __device__ __forceinline__ void conv_one(
    int i, const float* __restrict__ x,
    const float* __restrict__ w0, const float* __restrict__ w1,
    const float* __restrict__ w2, const float* __restrict__ w3)
{
    const float* src;
    __half* dst;
    int idx;
    if (i < XN4) {
        src = x; dst = g_xh; idx = i;
    } else {
        int r = (i - XN4) >> 16;          // WN4 = 65536
        idx = (i - XN4) & 65535;
        const float* srcs[4] = {w0, w1, w2, w3};
        src = srcs[r]; dst = g_w[r];
    }
    float4 v = ((const float4*)src)[idx];
    uint2 o;
    o.x = f2h2(v.x, v.y);
    o.y = f2h2(v.z, v.w);
    ((uint2*)dst)[idx] = o;
}

__global__ __launch_bounds__(256) void conv_all(
    const float* __restrict__ x,
    const float* __restrict__ w0, const float* __restrict__ w1,
    const float* __restrict__ w2, const float* __restrict__ w3)
{
    int i = blockIdx.x * blockDim.x + threadIdx.x;
    if (i >= CONV_HALF) return;
    conv_one(i, x, w0, w1, w2, w3);
    conv_one(i + CONV_HALF, x, w0, w1, w2, w3);
}

// ---------------------------------------------------------------------------
// HMMA GEMM (R13 structure): single-pass fp16, fp32 accum. 128x128 tile,
// K-chunk 64, 2-stage double buffer (loads issued BEFORE wait), 8 warps,
// 2 CTAs/SM. QKV fused: grid (64,4,3); final: fin=1.
// Q output (z==0) pre-scaled by log2(e)/sqrt(512).
// ---------------------------------------------------------------------------
#define TILE_BYTES 16384             // 128 rows x 128B
#define STAGE_BYTES (2 * TILE_BYTES) // A, W
#define GEMM_SMEM (2 * STAGE_BYTES)  // 64 KB

static __device__ __forceinline__ void load_stage(
    uint32_t sbase, int buf, int k0, int tid,
    const __half* tA, const __half* tW)
{
    uint32_t stb = sbase + (uint32_t)buf * STAGE_BYTES;
    const __half* t01[2] = {tA, tW};
#pragma unroll
    for (int i = 0; i < 8; i++) {
        int t = i >> 2;
        int idx = tid + (i & 3) * 256;
        int rr = (idx >> 3) & 127;
        int cc = idx & 7;
        uint32_t dst = stb + t * TILE_BYTES + rr * 128 + ((cc ^ (rr & 7)) * 16);
        cp16(dst, t01[t] + (size_t)rr * EMB + k0 + cc * 8);
    }
    CP_COMMIT();
}

__global__ __launch_bounds__(256, 2) void gemm_mma(
    const float* __restrict__ b0, const float* __restrict__ b1,
    const float* __restrict__ b2, float* __restrict__ Cext, int fin)
{
    extern __shared__ __align__(1024) char dsm[];
    const uint32_t sbase = smem_u32(dsm);

    const int z = blockIdx.z;
    const float* bias = fin ? b0 : (z == 0 ? b0 : (z == 1 ? b1 : b2));
    const __half* Aa = fin ? g_oh : g_xh;
    const __half* Bw = g_w[fin ? 3 : z];
    const float oscale = (!fin && z == 0) ? QSCALE : 1.0f;

    const int tid = threadIdx.x;
    const int lane = tid & 31;
    const int wid = tid >> 5;
    const int warp_m = wid >> 2;
    const int warp_n = wid & 3;
    const int bm = blockIdx.x * 128;
    const int bn = blockIdx.y * 128;

    const int lr = lane & 15;
    const int lh = lane >> 4;
    const int l7 = lane & 7;

    float acc[4][4][4];
#pragma unroll
    for (int mt = 0; mt < 4; mt++)
#pragma unroll
        for (int nt = 0; nt < 4; nt++)
#pragma unroll
            for (int j = 0; j < 4; j++) acc[mt][nt][j] = 0.f;

    const __half* tA = Aa + (size_t)bm * EMB;
    const __half* tB = Bw + (size_t)bn * EMB;

    load_stage(sbase, 0, 0, tid, tA, tB);

    const uint32_t arow_off = (uint32_t)(warp_m * 64 + lr) * 128;
    const uint32_t brow_off = (uint32_t)(warp_n * 32 + lr) * 128;

    for (int c = 0; c < 8; ++c) {
        const int buf = c & 1;
        if (c + 1 < 8) {
            load_stage(sbase, buf ^ 1, (c + 1) * 64, tid, tA, tB);
            CP_WAIT(1);
        } else {
            CP_WAIT(0);
        }
        __syncthreads();

        const uint32_t sA = sbase + buf * STAGE_BYTES;
        const uint32_t sB = sA + TILE_BYTES;

#pragma unroll
        for (int kk = 0; kk < 4; kk++) {
            const uint32_t ch = (uint32_t)(((kk * 2) | lh) ^ l7) * 16;
            uint32_t ah[4][4], bh[4][2];
#pragma unroll
            for (int mt = 0; mt < 4; mt++) {
                uint32_t off = arow_off + (uint32_t)(mt * 16) * 128 + ch;
                ldm_x4(ah[mt][0], ah[mt][1], ah[mt][2], ah[mt][3], sA + off);
            }
#pragma unroll
            for (int p = 0; p < 2; p++) {
                uint32_t off = brow_off + (uint32_t)(p * 16) * 128 + ch;
                uint32_t r0, r1, r2, r3;
                ldm_x4(r0, r1, r2, r3, sB + off);
                bh[p * 2][0] = r0; bh[p * 2][1] = r2;
                bh[p * 2 + 1][0] = r1; bh[p * 2 + 1][1] = r3;
            }
#pragma unroll
            for (int mt = 0; mt < 4; mt++)
#pragma unroll
                for (int nt = 0; nt < 4; nt++)
                    mma_f16(acc[mt][nt], ah[mt], bh[nt]);
        }
        __syncthreads();
    }

    // ---- epilogue ----
    const int g = lane >> 2;
    const int tg = lane & 3;
#pragma unroll
    for (int mt = 0; mt < 4; mt++) {
        int row = bm + warp_m * 64 + mt * 16 + g;
#pragma unroll
        for (int nt = 0; nt < 4; nt++) {
            int col = bn + warp_n * 32 + nt * 8 + tg * 2;
            float bx = bias[col], by = bias[col + 1];
            float v00 = (acc[mt][nt][0] + bx) * oscale, v01 = (acc[mt][nt][1] + by) * oscale;
            float v10 = (acc[mt][nt][2] + bx) * oscale, v11 = (acc[mt][nt][3] + by) * oscale;
            if (fin) {
                float2 a0 = {v00, v01}, a1 = {v10, v11};
                *(float2*)&Cext[(size_t)row * EMB + col] = a0;
                *(float2*)&Cext[(size_t)(row + 8) * EMB + col] = a1;
            } else {
                __half* dst = (z == 0) ? g_qh : ((z == 1) ? g_kh : g_vh);
                *(uint32_t*)&dst[(size_t)row * EMB + col] = f2h2(v00, v01);
                *(uint32_t*)&dst[(size_t)(row + 8) * EMB + col] = f2h2(v10, v11);
            }
        }
    }
}

// ---------------------------------------------------------------------------
// HMMA banded flash attention (R13 structure), no-max softmax, 2-stage K/V
// double buffer, with the chunk body SPECIALIZED into an interior fast path
// (compile-time plo=0/phi=3/typ=0: no guards, no masks) and a boundary path.
// One CTA per (b, h, 64-query tile), 4 warps. smem 32KB.
// ---------------------------------------------------------------------------
__global__ __launch_bounds__(128) void attn_mma()
{
    __shared__ __align__(1024) char smem_buf[32768];
    const uint32_t sb0 = smem_u32(smem_buf);

    const int tid = threadIdx.x;
    const int lane = tid & 31;
    const int wid = tid >> 5;
    const int q0 = blockIdx.x * 64;
    const int h = blockIdx.y;
    const int b = blockIdx.z;

    const int lr = lane & 15;
    const int lh = lane >> 4;
    const int l7 = lane & 7;
    const int g = lane >> 2;
    const int tg = lane & 3;

    const size_t tok0 = (size_t)b * SEQ;
    const int colh = h * DHEAD;

    // ---- stage Q (pre-scaled) into buf0 K-region, extract fragments ----
#pragma unroll
    for (int i = 0; i < 4; i++) {
        int idx = tid + i * 128;
        int rr = idx >> 3, cc = idx & 7;
        cp16(sb0 + rr * 128 + ((cc ^ (rr & 7)) * 16),
             g_qh + (tok0 + q0 + rr) * EMB + colh + cc * 8);
    }
    CP_COMMIT(); CP_WAIT(0); __syncthreads();

    uint32_t qh[4][4];
#pragma unroll
    for (int kk = 0; kk < 4; kk++) {
        uint32_t ch = (uint32_t)(((kk * 2) | lh) ^ l7) * 16;
        uint32_t off = (uint32_t)(wid * 16 + lr) * 128 + ch;
        ldm_x4(qh[kk][0], qh[kk][1], qh[kk][2], qh[kk][3], sb0 + off);
    }
    __syncthreads();

    float oacc[8][4];
#pragma unroll
    for (int j = 0; j < 8; j++)
#pragma unroll
        for (int c = 0; c < 4; c++) oacc[j][c] = 0.f;

    float l0 = 0.f, l8 = 0.f;

    const int qg0 = q0 + wid * 16 + g;
    const int qg8 = qg0 + 8;

    int klo_ = q0 - WINDOW; if (klo_ < 0) klo_ = 0;
    int khi_ = q0 + 64 + WINDOW; if (khi_ > SEQ) khi_ = SEQ;
    const int nch = (khi_ - klo_) >> 6;

    auto load_kv = [&](int buf, int kc) {
        uint32_t base = sb0 + (uint32_t)buf * 16384;
#pragma unroll
        for (int i = 0; i < 4; i++) {
            int idx = tid + i * 128;
            int rr = idx >> 3, cc = idx & 7;
            uint32_t so = rr * 128 + ((cc ^ (rr & 7)) * 16);
            cp16(base + so, g_kh + (tok0 + kc + rr) * EMB + colh + cc * 8);
            cp16(base + 8192 + so, g_vh + (tok0 + kc + rr) * EMB + colh + cc * 8);
        }
        CP_COMMIT();
    };

    // chunk body; plo/phi/typ become compile-time constants in the fast arm
    auto chunk_body = [&](int kc, uint32_t bK, uint32_t bV,
                          int plo, int phi, int typ) {
        // ---- S = Q K^T (log2-domain) ----
        float sacc[8][4];
#pragma unroll
        for (int p = 0; p < 4; p++) {
            bool act = (p >= plo && p <= phi);
#pragma unroll
            for (int j = 0; j < 2; j++)
#pragma unroll
                for (int cc = 0; cc < 4; cc++)
                    sacc[p * 2 + j][cc] = act ? 0.f : -1e30f;
        }
#pragma unroll
        for (int p = 0; p < 4; p++) {
            if (p < plo || p > phi) continue;    // warp-uniform skip
#pragma unroll
            for (int kk = 0; kk < 4; kk++) {
                uint32_t ch = (uint32_t)(((kk * 2) | lh) ^ l7) * 16;
                uint32_t off = (uint32_t)(p * 16 + lr) * 128 + ch;
                uint32_t r0, r1, r2, r3;
                ldm_x4(r0, r1, r2, r3, bK + off);
                uint32_t b0[2] = {r0, r2}, b1[2] = {r1, r3};
                mma_f16(sacc[p * 2], qh[kk], b0);
                mma_f16(sacc[p * 2 + 1], qh[kk], b1);
            }
        }

        // ---- mask (boundary chunks only) ----
        if (typ) {
#pragma unroll
            for (int j = 0; j < 8; j++) {
                int kg = kc + j * 8 + tg * 2;
                if (abs(qg0 - kg) > WINDOW)       sacc[j][0] = -1e30f;
                if (abs(qg0 - (kg + 1)) > WINDOW) sacc[j][1] = -1e30f;
                if (abs(qg8 - kg) > WINDOW)       sacc[j][2] = -1e30f;
                if (abs(qg8 - (kg + 1)) > WINDOW) sacc[j][3] = -1e30f;
            }
        }

        // ---- exp2 (no max subtraction), pack, accumulate l ----
        uint32_t phg[8], phg8[8];
#pragma unroll
        for (int j = 0; j < 8; j++) {
            float p0 = ex2f(sacc[j][0]);
            float p1 = ex2f(sacc[j][1]);
            float p2 = ex2f(sacc[j][2]);
            float p3 = ex2f(sacc[j][3]);
            l0 += p0 + p1; l8 += p2 + p3;
            phg[j]  = f2h2(p0, p1);
            phg8[j] = f2h2(p2, p3);
        }

        // ---- O += P V ----
#pragma unroll
        for (int t = 0; t < 4; t++) {
            if (t < plo || t > phi) continue;    // warp-uniform skip
            uint32_t vh[8][2];
            int row = t * 16 + lr;               // key row for this lane
            uint32_t rbase = bV + (uint32_t)row * 128;
            uint32_t rsw = (uint32_t)(row & 7);
#pragma unroll
            for (int pp = 0; pp < 4; pp++) {
                uint32_t d = (uint32_t)(pp * 2) + (uint32_t)lh;  // dim group (16B)
                uint32_t addr = rbase + ((d ^ rsw) * 16);
                uint32_t r0, r1, r2, r3;
                ldm_x4_t(r0, r1, r2, r3, addr);
                vh[pp * 2][0] = r0;     vh[pp * 2][1] = r1;
                vh[pp * 2 + 1][0] = r2; vh[pp * 2 + 1][1] = r3;
            }
            uint32_t pa_h[4] = {phg[2 * t], phg8[2 * t], phg[2 * t + 1], phg8[2 * t + 1]};
#pragma unroll
            for (int j = 0; j < 8; j++)
                mma_f16(oacc[j], pa_h, vh[j]);
        }
    };

    load_kv(0, klo_);

    for (int c = 0; c < nch; c++) {
        const int kc = klo_ + c * 64;
        const int buf = c & 1;
        const int typ = (kc == q0 - 128) ? 1 : ((kc == q0 + 128) ? 2 : 0);

        CP_WAIT(0);
        __syncthreads();
        if (c + 1 < nch) load_kv(buf ^ 1, kc + 64);

        const uint32_t bK = sb0 + (uint32_t)buf * 16384;
        const uint32_t bV = bK + 8192;

        if (typ == 0) {
            chunk_body(kc, bK, bV, 0, 3, 0);          // fast interior path
        } else {
            const int plo = (typ == 1) ? wid : 0;
            const int phi = (typ == 2) ? wid : 3;
            chunk_body(kc, bK, bV, plo, phi, typ);    // boundary path
        }
    }

    // ---- single deferred l reduction across the 4 lanes of each row ----
    l0 += __shfl_xor_sync(0xffffffffu, l0, 1);
    l0 += __shfl_xor_sync(0xffffffffu, l0, 2);
    l8 += __shfl_xor_sync(0xffffffffu, l8, 1);
    l8 += __shfl_xor_sync(0xffffffffu, l8, 2);

    // ---- epilogue: normalize, store plain fp16 ----
    float il0 = 1.f / l0, il8 = 1.f / l8;
    size_t r0base = (tok0 + qg0) * EMB + colh;
    size_t r8base = (tok0 + qg8) * EMB + colh;
#pragma unroll
    for (int j = 0; j < 8; j++) {
        int col = j * 8 + tg * 2;
        *(uint32_t*)&g_oh[r0base + col] = f2h2(oacc[j][0] * il0, oacc[j][1] * il0);
        *(uint32_t*)&g_oh[r8base + col] = f2h2(oacc[j][2] * il8, oacc[j][3] * il8);
    }
}

// ---------------------------------------------------------------------------
extern "C" void kernel_launch(void* const* d_in, const int* in_sizes, int n_in,
                              void* d_out, int out_size)
{
    const float* x  = (const float*)d_in[0];
    const float* Wq = (const float*)d_in[1];
    const float* bq = (const float*)d_in[2];
    const float* Wk = (const float*)d_in[3];
    const float* bk = (const float*)d_in[4];
    const float* Wv = (const float*)d_in[5];
    const float* bv = (const float*)d_in[6];
    const float* Wo = (const float*)d_in[7];
    const float* bo = (const float*)d_in[8];
    float* out = (float*)d_out;

    cudaFuncSetAttribute(gemm_mma, cudaFuncAttributeMaxDynamicSharedMemorySize, GEMM_SMEM);

    conv_all<<<(CONV_HALF + 255) / 256, 256>>>(x, Wq, Wk, Wv, Wo);

    gemm_mma<<<dim3(MTOT / 128, EMB / 128, 3), 256, GEMM_SMEM>>>(bq, bk, bv, nullptr, 0);

    attn_mma<<<dim3(SEQ / 64, NHEAD, BATCH), 128>>>();

    gemm_mma<<<dim3(MTOT / 128, EMB / 128, 1), 256, GEMM_SMEM>>>(bo, nullptr, nullptr, out, 1);
}

// round 16
// speedup vs baseline: 1.0735x; 1.0042x over previous
#include <cuda_runtime.h>
#include <cuda_fp16.h>
#include <math.h>
#include <stdint.h>

#define EMB 512
#define NHEAD 8
#define DHEAD 64
#define SEQ 4096
#define BATCH 2
#define WINDOW 128
#define MTOT (BATCH * SEQ)   // 8192

// fp16 operands ([token][EMB] layout)
__device__ __half g_xh[(size_t)MTOT * EMB];
__device__ __half g_qh[(size_t)MTOT * EMB];   // pre-scaled by log2(e)/sqrt(512)
__device__ __half g_kh[(size_t)MTOT * EMB];
__device__ __half g_vh[(size_t)MTOT * EMB];
__device__ __half g_oh[(size_t)MTOT * EMB];
__device__ __half g_w[4][EMB * EMB];          // fp16 weights

// ---------------------------------------------------------------------------
// helpers (base sm_103 ISA: cp.async + ldmatrix + mma.sync)
// ---------------------------------------------------------------------------
static __device__ __forceinline__ uint32_t smem_u32(const void* p) {
    uint32_t a;
    asm("{ .reg .u64 t; cvta.to.shared.u64 t, %1; cvt.u32.u64 %0, t; }"
        : "=r"(a) : "l"(p));
    return a;
}
static __device__ __forceinline__ void cp16(uint32_t dst, const void* src) {
    asm volatile("cp.async.cg.shared.global [%0], [%1], 16;" :: "r"(dst), "l"(src));
}
#define CP_COMMIT() asm volatile("cp.async.commit_group;" ::: "memory")
#define CP_WAIT(n)  asm volatile("cp.async.wait_group %0;" :: "n"(n) : "memory")

static __device__ __forceinline__ void ldm_x4(uint32_t& r0, uint32_t& r1,
                                              uint32_t& r2, uint32_t& r3, uint32_t a) {
    asm volatile("ldmatrix.sync.aligned.m8n8.x4.shared.b16 {%0,%1,%2,%3}, [%4];"
                 : "=r"(r0), "=r"(r1), "=r"(r2), "=r"(r3) : "r"(a));
}
static __device__ __forceinline__ void ldm_x4_t(uint32_t& r0, uint32_t& r1,
                                                uint32_t& r2, uint32_t& r3, uint32_t a) {
    asm volatile("ldmatrix.sync.aligned.m8n8.x4.trans.shared.b16 {%0,%1,%2,%3}, [%4];"
                 : "=r"(r0), "=r"(r1), "=r"(r2), "=r"(r3) : "r"(a));
}
static __device__ __forceinline__ void mma_f16(float* d, const uint32_t* a, const uint32_t* b) {
    asm volatile(
        "mma.sync.aligned.m16n8k16.row.col.f32.f16.f16.f32 "
        "{%0,%1,%2,%3}, {%4,%5,%6,%7}, {%8,%9}, {%0,%1,%2,%3};"
        : "+f"(d[0]), "+f"(d[1]), "+f"(d[2]), "+f"(d[3])
        : "r"(a[0]), "r"(a[1]), "r"(a[2]), "r"(a[3]), "r"(b[0]), "r"(b[1]));
}
static __device__ __forceinline__ uint32_t f2h2(float a, float b) {
    __half2 t = __floats2half2_rn(a, b);   // low = a, high = b
    return *(uint32_t*)&t;
}
static __device__ __forceinline__ float ex2f(float x) {
    float y;
    asm("ex2.approx.ftz.f32 %0, %1;" : "=f"(y) : "f"(x));
    return y;
}

// Q prescale: log2(e) / sqrt(512)
#define QSCALE 0.063758715849976f

// ---------------------------------------------------------------------------
// merged conversion: region 0 = x, regions 1..4 = W[0..3]; 2 units/thread (ILP)
// ---------------------------------------------------------------------------
#define XN4 (MTOT * EMB / 4)     // 1048576
#define WN4 (EMB * EMB / 4)      // 65536
#define CONV_TOT (XN4 + 4 * WN4) // 1310720
#define CONV_HALF (CONV_TOT / 2) // 655360

static __device__ __forceinline__ void conv_one(
    int i, const float* __restrict__ x,
    const float* __restrict__ w0, const float* __restrict__ w1,
    const float* __restrict__ w2, const float* __restrict__ w3)
{
    const float* src;
    __half* dst;
    int idx;
    if (i < XN4) {
        src = x; dst = g_xh; idx = i;
    } else {
        int r = (i - XN4) >> 16;          // WN4 = 65536
        idx = (i - XN4) & 65535;
        const float* srcs[4] = {w0, w1, w2, w3};
        src = srcs[r]; dst = g_w[r];
    }
    float4 v = ((const float4*)src)[idx];
    uint2 o;
    o.x = f2h2(v.x, v.y);
    o.y = f2h2(v.z, v.w);
    ((uint2*)dst)[idx] = o;
}

__global__ __launch_bounds__(256) void conv_all(
    const float* __restrict__ x,
    const float* __restrict__ w0, const float* __restrict__ w1,
    const float* __restrict__ w2, const float* __restrict__ w3)
{
    int i = blockIdx.x * blockDim.x + threadIdx.x;
    if (i >= CONV_HALF) return;
    conv_one(i, x, w0, w1, w2, w3);
    conv_one(i + CONV_HALF, x, w0, w1, w2, w3);
}

// ---------------------------------------------------------------------------
// HMMA GEMM (R13/R15 structure): single-pass fp16, fp32 accum. 128x128 tile,
// K-chunk 64, 2-stage double buffer (loads issued BEFORE wait), 8 warps,
// 2 CTAs/SM. QKV fused: grid (64,4,3); final: fin=1.
// Q output (z==0) pre-scaled by log2(e)/sqrt(512).
// ---------------------------------------------------------------------------
#define TILE_BYTES 16384             // 128 rows x 128B
#define STAGE_BYTES (2 * TILE_BYTES) // A, W
#define GEMM_SMEM (2 * STAGE_BYTES)  // 64 KB

static __device__ __forceinline__ void load_stage(
    uint32_t sbase, int buf, int k0, int tid,
    const __half* tA, const __half* tW)
{
    uint32_t stb = sbase + (uint32_t)buf * STAGE_BYTES;
    const __half* t01[2] = {tA, tW};
#pragma unroll
    for (int i = 0; i < 8; i++) {
        int t = i >> 2;
        int idx = tid + (i & 3) * 256;
        int rr = (idx >> 3) & 127;
        int cc = idx & 7;
        uint32_t dst = stb + t * TILE_BYTES + rr * 128 + ((cc ^ (rr & 7)) * 16);
        cp16(dst, t01[t] + (size_t)rr * EMB + k0 + cc * 8);
    }
    CP_COMMIT();
}

__global__ __launch_bounds__(256, 2) void gemm_mma(
    const float* __restrict__ b0, const float* __restrict__ b1,
    const float* __restrict__ b2, float* __restrict__ Cext, int fin)
{
    extern __shared__ __align__(1024) char dsm[];
    const uint32_t sbase = smem_u32(dsm);

    const int z = blockIdx.z;
    const float* bias = fin ? b0 : (z == 0 ? b0 : (z == 1 ? b1 : b2));
    const __half* Aa = fin ? g_oh : g_xh;
    const __half* Bw = g_w[fin ? 3 : z];
    const float oscale = (!fin && z == 0) ? QSCALE : 1.0f;

    const int tid = threadIdx.x;
    const int lane = tid & 31;
    const int wid = tid >> 5;
    const int warp_m = wid >> 2;
    const int warp_n = wid & 3;
    const int bm = blockIdx.x * 128;
    const int bn = blockIdx.y * 128;

    const int lr = lane & 15;
    const int lh = lane >> 4;
    const int l7 = lane & 7;

    float acc[4][4][4];
#pragma unroll
    for (int mt = 0; mt < 4; mt++)
#pragma unroll
        for (int nt = 0; nt < 4; nt++)
#pragma unroll
            for (int j = 0; j < 4; j++) acc[mt][nt][j] = 0.f;

    const __half* tA = Aa + (size_t)bm * EMB;
    const __half* tB = Bw + (size_t)bn * EMB;

    load_stage(sbase, 0, 0, tid, tA, tB);

    const uint32_t arow_off = (uint32_t)(warp_m * 64 + lr) * 128;
    const uint32_t brow_off = (uint32_t)(warp_n * 32 + lr) * 128;

    for (int c = 0; c < 8; ++c) {
        const int buf = c & 1;
        if (c + 1 < 8) {
            load_stage(sbase, buf ^ 1, (c + 1) * 64, tid, tA, tB);
            CP_WAIT(1);
        } else {
            CP_WAIT(0);
        }
        __syncthreads();

        const uint32_t sA = sbase + buf * STAGE_BYTES;
        const uint32_t sB = sA + TILE_BYTES;

#pragma unroll
        for (int kk = 0; kk < 4; kk++) {
            const uint32_t ch = (uint32_t)(((kk * 2) | lh) ^ l7) * 16;
            uint32_t ah[4][4], bh[4][2];
#pragma unroll
            for (int mt = 0; mt < 4; mt++) {
                uint32_t off = arow_off + (uint32_t)(mt * 16) * 128 + ch;
                ldm_x4(ah[mt][0], ah[mt][1], ah[mt][2], ah[mt][3], sA + off);
            }
#pragma unroll
            for (int p = 0; p < 2; p++) {
                uint32_t off = brow_off + (uint32_t)(p * 16) * 128 + ch;
                uint32_t r0, r1, r2, r3;
                ldm_x4(r0, r1, r2, r3, sB + off);
                bh[p * 2][0] = r0; bh[p * 2][1] = r2;
                bh[p * 2 + 1][0] = r1; bh[p * 2 + 1][1] = r3;
            }
#pragma unroll
            for (int mt = 0; mt < 4; mt++)
#pragma unroll
                for (int nt = 0; nt < 4; nt++)
                    mma_f16(acc[mt][nt], ah[mt], bh[nt]);
        }
        __syncthreads();
    }

    // ---- epilogue ----
    const int g = lane >> 2;
    const int tg = lane & 3;
#pragma unroll
    for (int mt = 0; mt < 4; mt++) {
        int row = bm + warp_m * 64 + mt * 16 + g;
#pragma unroll
        for (int nt = 0; nt < 4; nt++) {
            int col = bn + warp_n * 32 + nt * 8 + tg * 2;
            float bx = bias[col], by = bias[col + 1];
            float v00 = (acc[mt][nt][0] + bx) * oscale, v01 = (acc[mt][nt][1] + by) * oscale;
            float v10 = (acc[mt][nt][2] + bx) * oscale, v11 = (acc[mt][nt][3] + by) * oscale;
            if (fin) {
                float2 a0 = {v00, v01}, a1 = {v10, v11};
                *(float2*)&Cext[(size_t)row * EMB + col] = a0;
                *(float2*)&Cext[(size_t)(row + 8) * EMB + col] = a1;
            } else {
                __half* dst = (z == 0) ? g_qh : ((z == 1) ? g_kh : g_vh);
                *(uint32_t*)&dst[(size_t)row * EMB + col] = f2h2(v00, v01);
                *(uint32_t*)&dst[(size_t)(row + 8) * EMB + col] = f2h2(v10, v11);
            }
        }
    }
}

// ---------------------------------------------------------------------------
// HMMA banded flash attention, no-max softmax, 2-stage K/V double buffer.
// FUSED per-key-group dataflow: for each active 16-key group t:
//   [4 K-ldm + 8 S-MMA] -> [mask (boundary only)] -> [8 ex2 + 4 f2h2]
//   -> [4 V-ldm.trans + 8 PV-MMA]
// Minimal live registers; skipped groups touch nothing (exp(masked)=0 would
// contribute 0 to l, so skipping is exact).
// One CTA per (b, h, 64-query tile), 4 warps. smem 32KB.
// ---------------------------------------------------------------------------
__global__ __launch_bounds__(128) void attn_mma()
{
    __shared__ __align__(1024) char smem_buf[32768];
    const uint32_t sb0 = smem_u32(smem_buf);

    const int tid = threadIdx.x;
    const int lane = tid & 31;
    const int wid = tid >> 5;
    const int q0 = blockIdx.x * 64;
    const int h = blockIdx.y;
    const int b = blockIdx.z;

    const int lr = lane & 15;
    const int lh = lane >> 4;
    const int l7 = lane & 7;
    const int g = lane >> 2;
    const int tg = lane & 3;

    const size_t tok0 = (size_t)b * SEQ;
    const int colh = h * DHEAD;

    // ---- stage Q (pre-scaled) into buf0 K-region, extract fragments ----
#pragma unroll
    for (int i = 0; i < 4; i++) {
        int idx = tid + i * 128;
        int rr = idx >> 3, cc = idx & 7;
        cp16(sb0 + rr * 128 + ((cc ^ (rr & 7)) * 16),
             g_qh + (tok0 + q0 + rr) * EMB + colh + cc * 8);
    }
    CP_COMMIT(); CP_WAIT(0); __syncthreads();

    uint32_t qh[4][4];
#pragma unroll
    for (int kk = 0; kk < 4; kk++) {
        uint32_t ch = (uint32_t)(((kk * 2) | lh) ^ l7) * 16;
        uint32_t off = (uint32_t)(wid * 16 + lr) * 128 + ch;
        ldm_x4(qh[kk][0], qh[kk][1], qh[kk][2], qh[kk][3], sb0 + off);
    }
    __syncthreads();

    float oacc[8][4];
#pragma unroll
    for (int j = 0; j < 8; j++)
#pragma unroll
        for (int c = 0; c < 4; c++) oacc[j][c] = 0.f;

    float l0 = 0.f, l8 = 0.f;

    const int qg0 = q0 + wid * 16 + g;
    const int qg8 = qg0 + 8;

    int klo_ = q0 - WINDOW; if (klo_ < 0) klo_ = 0;
    int khi_ = q0 + 64 + WINDOW; if (khi_ > SEQ) khi_ = SEQ;
    const int nch = (khi_ - klo_) >> 6;

    auto load_kv = [&](int buf, int kc) {
        uint32_t base = sb0 + (uint32_t)buf * 16384;
#pragma unroll
        for (int i = 0; i < 4; i++) {
            int idx = tid + i * 128;
            int rr = idx >> 3, cc = idx & 7;
            uint32_t so = rr * 128 + ((cc ^ (rr & 7)) * 16);
            cp16(base + so, g_kh + (tok0 + kc + rr) * EMB + colh + cc * 8);
            cp16(base + 8192 + so, g_vh + (tok0 + kc + rr) * EMB + colh + cc * 8);
        }
        CP_COMMIT();
    };

    // fused per-group chunk body; plo/phi/typ constant-fold in the fast arm
    auto chunk_body = [&](int kc, uint32_t bK, uint32_t bV,
                          int plo, int phi, int typ) {
#pragma unroll
        for (int t = 0; t < 4; t++) {
            if (t < plo || t > phi) continue;    // warp-uniform skip (exact)

            // ---- S for this 16-key group (j = 2t, 2t+1) ----
            float s0[4] = {0.f, 0.f, 0.f, 0.f};
            float s1[4] = {0.f, 0.f, 0.f, 0.f};
#pragma unroll
            for (int kk = 0; kk < 4; kk++) {
                uint32_t ch = (uint32_t)(((kk * 2) | lh) ^ l7) * 16;
                uint32_t off = (uint32_t)(t * 16 + lr) * 128 + ch;
                uint32_t r0, r1, r2, r3;
                ldm_x4(r0, r1, r2, r3, bK + off);
                uint32_t kb0[2] = {r0, r2}, kb1[2] = {r1, r3};
                mma_f16(s0, qh[kk], kb0);
                mma_f16(s1, qh[kk], kb1);
            }

            // ---- mask (boundary chunks only) ----
            if (typ) {
                int kg0 = kc + t * 16 + tg * 2;   // keys of j=2t
                int kg1 = kg0 + 8;                // keys of j=2t+1
                if (abs(qg0 - kg0) > WINDOW)       s0[0] = -1e30f;
                if (abs(qg0 - (kg0 + 1)) > WINDOW) s0[1] = -1e30f;
                if (abs(qg8 - kg0) > WINDOW)       s0[2] = -1e30f;
                if (abs(qg8 - (kg0 + 1)) > WINDOW) s0[3] = -1e30f;
                if (abs(qg0 - kg1) > WINDOW)       s1[0] = -1e30f;
                if (abs(qg0 - (kg1 + 1)) > WINDOW) s1[1] = -1e30f;
                if (abs(qg8 - kg1) > WINDOW)       s1[2] = -1e30f;
                if (abs(qg8 - (kg1 + 1)) > WINDOW) s1[3] = -1e30f;
            }

            // ---- exp2 (no max subtraction: logits bounded), pack, l ----
            float p00 = ex2f(s0[0]), p01 = ex2f(s0[1]);
            float p02 = ex2f(s0[2]), p03 = ex2f(s0[3]);
            float p10 = ex2f(s1[0]), p11 = ex2f(s1[1]);
            float p12 = ex2f(s1[2]), p13 = ex2f(s1[3]);
            l0 += p00 + p01 + p10 + p11;
            l8 += p02 + p03 + p12 + p13;
            uint32_t pa[4] = {f2h2(p00, p01), f2h2(p02, p03),
                              f2h2(p10, p11), f2h2(p12, p13)};

            // ---- O += P V for this group ----
            int row = t * 16 + lr;
            uint32_t rbase = bV + (uint32_t)row * 128;
            uint32_t rsw = (uint32_t)(row & 7);
#pragma unroll
            for (int pp = 0; pp < 4; pp++) {
                uint32_t d = (uint32_t)(pp * 2) + (uint32_t)lh;
                uint32_t r0, r1, r2, r3;
                ldm_x4_t(r0, r1, r2, r3, rbase + ((d ^ rsw) * 16));
                uint32_t vb0[2] = {r0, r1}, vb1[2] = {r2, r3};
                mma_f16(oacc[pp * 2], pa, vb0);
                mma_f16(oacc[pp * 2 + 1], pa, vb1);
            }
        }
    };

    load_kv(0, klo_);

    for (int c = 0; c < nch; c++) {
        const int kc = klo_ + c * 64;
        const int buf = c & 1;
        const int typ = (kc == q0 - 128) ? 1 : ((kc == q0 + 128) ? 2 : 0);

        CP_WAIT(0);
        __syncthreads();
        if (c + 1 < nch) load_kv(buf ^ 1, kc + 64);

        const uint32_t bK = sb0 + (uint32_t)buf * 16384;
        const uint32_t bV = bK + 8192;

        if (typ == 0) {
            chunk_body(kc, bK, bV, 0, 3, 0);          // fast interior path
        } else {
            const int plo = (typ == 1) ? wid : 0;
            const int phi = (typ == 2) ? wid : 3;
            chunk_body(kc, bK, bV, plo, phi, typ);    // boundary path
        }
    }

    // ---- single deferred l reduction across the 4 lanes of each row ----
    l0 += __shfl_xor_sync(0xffffffffu, l0, 1);
    l0 += __shfl_xor_sync(0xffffffffu, l0, 2);
    l8 += __shfl_xor_sync(0xffffffffu, l8, 1);
    l8 += __shfl_xor_sync(0xffffffffu, l8, 2);

    // ---- epilogue: normalize, store plain fp16 ----
    float il0 = 1.f / l0, il8 = 1.f / l8;
    size_t r0base = (tok0 + qg0) * EMB + colh;
    size_t r8base = (tok0 + qg8) * EMB + colh;
#pragma unroll
    for (int j = 0; j < 8; j++) {
        int col = j * 8 + tg * 2;
        *(uint32_t*)&g_oh[r0base + col] = f2h2(oacc[j][0] * il0, oacc[j][1] * il0);
        *(uint32_t*)&g_oh[r8base + col] = f2h2(oacc[j][2] * il8, oacc[j][3] * il8);
    }
}

// ---------------------------------------------------------------------------
extern "C" void kernel_launch(void* const* d_in, const int* in_sizes, int n_in,
                              void* d_out, int out_size)
{
    const float* x  = (const float*)d_in[0];
    const float* Wq = (const float*)d_in[1];
    const float* bq = (const float*)d_in[2];
    const float* Wk = (const float*)d_in[3];
    const float* bk = (const float*)d_in[4];
    const float* Wv = (const float*)d_in[5];
    const float* bv = (const float*)d_in[6];
    const float* Wo = (const float*)d_in[7];
    const float* bo = (const float*)d_in[8];
    float* out = (float*)d_out;

    cudaFuncSetAttribute(gemm_mma, cudaFuncAttributeMaxDynamicSharedMemorySize, GEMM_SMEM);

    conv_all<<<(CONV_HALF + 255) / 256, 256>>>(x, Wq, Wk, Wv, Wo);

    gemm_mma<<<dim3(MTOT / 128, EMB / 128, 3), 256, GEMM_SMEM>>>(bq, bk, bv, nullptr, 0);

    attn_mma<<<dim3(SEQ / 64, NHEAD, BATCH), 128>>>();

    gemm_mma<<<dim3(MTOT / 128, EMB / 128, 1), 256, GEMM_SMEM>>>(bo, nullptr, nullptr, out, 1);
}

// round 17
// speedup vs baseline: 1.0898x; 1.0151x over previous
#include <cuda_runtime.h>
#include <cuda_fp16.h>
#include <math.h>
#include <stdint.h>

#define EMB 512
#define NHEAD 8
#define DHEAD 64
#define SEQ 4096
#define BATCH 2
#define WINDOW 128
#define MTOT (BATCH * SEQ)   // 8192

// fp16 operands ([token][EMB] layout)
__device__ __half g_xh[(size_t)MTOT * EMB];
__device__ __half g_qh[(size_t)MTOT * EMB];   // pre-scaled by log2(e)/sqrt(512)
__device__ __half g_kh[(size_t)MTOT * EMB];
__device__ __half g_vh[(size_t)MTOT * EMB];
__device__ __half g_oh[(size_t)MTOT * EMB];
__device__ __half g_w[4][EMB * EMB];          // fp16 weights

// ---------------------------------------------------------------------------
// helpers (base sm_103 ISA: cp.async + ldmatrix + mma.sync)
// ---------------------------------------------------------------------------
static __device__ __forceinline__ uint32_t smem_u32(const void* p) {
    uint32_t a;
    asm("{ .reg .u64 t; cvta.to.shared.u64 t, %1; cvt.u32.u64 %0, t; }"
        : "=r"(a) : "l"(p));
    return a;
}
static __device__ __forceinline__ void cp16(uint32_t dst, const void* src) {
    asm volatile("cp.async.cg.shared.global [%0], [%1], 16;" :: "r"(dst), "l"(src));
}
#define CP_COMMIT() asm volatile("cp.async.commit_group;" ::: "memory")
#define CP_WAIT(n)  asm volatile("cp.async.wait_group %0;" :: "n"(n) : "memory")

static __device__ __forceinline__ void ldm_x4(uint32_t& r0, uint32_t& r1,
                                              uint32_t& r2, uint32_t& r3, uint32_t a) {
    asm volatile("ldmatrix.sync.aligned.m8n8.x4.shared.b16 {%0,%1,%2,%3}, [%4];"
                 : "=r"(r0), "=r"(r1), "=r"(r2), "=r"(r3) : "r"(a));
}
static __device__ __forceinline__ void ldm_x4_t(uint32_t& r0, uint32_t& r1,
                                                uint32_t& r2, uint32_t& r3, uint32_t a) {
    asm volatile("ldmatrix.sync.aligned.m8n8.x4.trans.shared.b16 {%0,%1,%2,%3}, [%4];"
                 : "=r"(r0), "=r"(r1), "=r"(r2), "=r"(r3) : "r"(a));
}
static __device__ __forceinline__ void mma_f16(float* d, const uint32_t* a, const uint32_t* b) {
    asm volatile(
        "mma.sync.aligned.m16n8k16.row.col.f32.f16.f16.f32 "
        "{%0,%1,%2,%3}, {%4,%5,%6,%7}, {%8,%9}, {%0,%1,%2,%3};"
        : "+f"(d[0]), "+f"(d[1]), "+f"(d[2]), "+f"(d[3])
        : "r"(a[0]), "r"(a[1]), "r"(a[2]), "r"(a[3]), "r"(b[0]), "r"(b[1]));
}
static __device__ __forceinline__ uint32_t f2h2(float a, float b) {
    __half2 t = __floats2half2_rn(a, b);   // low = a, high = b
    return *(uint32_t*)&t;
}
static __device__ __forceinline__ float ex2f(float x) {
    float y;
    asm("ex2.approx.ftz.f32 %0, %1;" : "=f"(y) : "f"(x));
    return y;
}

// Q prescale: log2(e) / sqrt(512)
#define QSCALE 0.063758715849976f

// ---------------------------------------------------------------------------
// merged conversion: region 0 = x, regions 1..4 = W[0..3]; 4 units/thread (MLP 4)
// ---------------------------------------------------------------------------
#define XN4 (MTOT * EMB / 4)     // 1048576
#define WN4 (EMB * EMB / 4)      // 65536
#define CONV_TOT (XN4 + 4 * WN4) // 1310720
#define CONV_QTR (CONV_TOT / 4)  // 327680

static __device__ __forceinline__ void conv_one(
    int i, const float* __restrict__ x,
    const float* __restrict__ w0, const float* __restrict__ w1,
    const float* __restrict__ w2, const float* __restrict__ w3)
{
    const float* src;
    __half* dst;
    int idx;
    if (i < XN4) {
        src = x; dst = g_xh; idx = i;
    } else {
        int r = (i - XN4) >> 16;          // WN4 = 65536
        idx = (i - XN4) & 65535;
        const float* srcs[4] = {w0, w1, w2, w3};
        src = srcs[r]; dst = g_w[r];
    }
    float4 v = ((const float4*)src)[idx];
    uint2 o;
    o.x = f2h2(v.x, v.y);
    o.y = f2h2(v.z, v.w);
    ((uint2*)dst)[idx] = o;
}

__global__ __launch_bounds__(256) void conv_all(
    const float* __restrict__ x,
    const float* __restrict__ w0, const float* __restrict__ w1,
    const float* __restrict__ w2, const float* __restrict__ w3)
{
    int i = blockIdx.x * blockDim.x + threadIdx.x;
    if (i >= CONV_QTR) return;
    conv_one(i, x, w0, w1, w2, w3);
    conv_one(i + CONV_QTR, x, w0, w1, w2, w3);
    conv_one(i + 2 * CONV_QTR, x, w0, w1, w2, w3);
    conv_one(i + 3 * CONV_QTR, x, w0, w1, w2, w3);
}

// ---------------------------------------------------------------------------
// HMMA GEMM (R13/R15 structure): single-pass fp16, fp32 accum. 128x128 tile,
// K-chunk 64, 2-stage double buffer (loads issued BEFORE wait), 8 warps,
// 2 CTAs/SM. QKV fused: grid (64,4,3); final: fin=1.
// Q output (z==0) pre-scaled by log2(e)/sqrt(512).
// ---------------------------------------------------------------------------
#define TILE_BYTES 16384             // 128 rows x 128B
#define STAGE_BYTES (2 * TILE_BYTES) // A, W
#define GEMM_SMEM (2 * STAGE_BYTES)  // 64 KB

static __device__ __forceinline__ void load_stage(
    uint32_t sbase, int buf, int k0, int tid,
    const __half* tA, const __half* tW)
{
    uint32_t stb = sbase + (uint32_t)buf * STAGE_BYTES;
    const __half* t01[2] = {tA, tW};
#pragma unroll
    for (int i = 0; i < 8; i++) {
        int t = i >> 2;
        int idx = tid + (i & 3) * 256;
        int rr = (idx >> 3) & 127;
        int cc = idx & 7;
        uint32_t dst = stb + t * TILE_BYTES + rr * 128 + ((cc ^ (rr & 7)) * 16);
        cp16(dst, t01[t] + (size_t)rr * EMB + k0 + cc * 8);
    }
    CP_COMMIT();
}

__global__ __launch_bounds__(256, 2) void gemm_mma(
    const float* __restrict__ b0, const float* __restrict__ b1,
    const float* __restrict__ b2, float* __restrict__ Cext, int fin)
{
    extern __shared__ __align__(1024) char dsm[];
    const uint32_t sbase = smem_u32(dsm);

    const int z = blockIdx.z;
    const float* bias = fin ? b0 : (z == 0 ? b0 : (z == 1 ? b1 : b2));
    const __half* Aa = fin ? g_oh : g_xh;
    const __half* Bw = g_w[fin ? 3 : z];
    const float oscale = (!fin && z == 0) ? QSCALE : 1.0f;

    const int tid = threadIdx.x;
    const int lane = tid & 31;
    const int wid = tid >> 5;
    const int warp_m = wid >> 2;
    const int warp_n = wid & 3;
    const int bm = blockIdx.x * 128;
    const int bn = blockIdx.y * 128;

    const int lr = lane & 15;
    const int lh = lane >> 4;
    const int l7 = lane & 7;

    float acc[4][4][4];
#pragma unroll
    for (int mt = 0; mt < 4; mt++)
#pragma unroll
        for (int nt = 0; nt < 4; nt++)
#pragma unroll
            for (int j = 0; j < 4; j++) acc[mt][nt][j] = 0.f;

    const __half* tA = Aa + (size_t)bm * EMB;
    const __half* tB = Bw + (size_t)bn * EMB;

    load_stage(sbase, 0, 0, tid, tA, tB);

    const uint32_t arow_off = (uint32_t)(warp_m * 64 + lr) * 128;
    const uint32_t brow_off = (uint32_t)(warp_n * 32 + lr) * 128;

    for (int c = 0; c < 8; ++c) {
        const int buf = c & 1;
        if (c + 1 < 8) {
            load_stage(sbase, buf ^ 1, (c + 1) * 64, tid, tA, tB);
            CP_WAIT(1);
        } else {
            CP_WAIT(0);
        }
        __syncthreads();

        const uint32_t sA = sbase + buf * STAGE_BYTES;
        const uint32_t sB = sA + TILE_BYTES;

#pragma unroll
        for (int kk = 0; kk < 4; kk++) {
            const uint32_t ch = (uint32_t)(((kk * 2) | lh) ^ l7) * 16;
            uint32_t ah[4][4], bh[4][2];
#pragma unroll
            for (int mt = 0; mt < 4; mt++) {
                uint32_t off = arow_off + (uint32_t)(mt * 16) * 128 + ch;
                ldm_x4(ah[mt][0], ah[mt][1], ah[mt][2], ah[mt][3], sA + off);
            }
#pragma unroll
            for (int p = 0; p < 2; p++) {
                uint32_t off = brow_off + (uint32_t)(p * 16) * 128 + ch;
                uint32_t r0, r1, r2, r3;
                ldm_x4(r0, r1, r2, r3, sB + off);
                bh[p * 2][0] = r0; bh[p * 2][1] = r2;
                bh[p * 2 + 1][0] = r1; bh[p * 2 + 1][1] = r3;
            }
#pragma unroll
            for (int mt = 0; mt < 4; mt++)
#pragma unroll
                for (int nt = 0; nt < 4; nt++)
                    mma_f16(acc[mt][nt], ah[mt], bh[nt]);
        }
        __syncthreads();
    }

    // ---- epilogue ----
    const int g = lane >> 2;
    const int tg = lane & 3;
#pragma unroll
    for (int mt = 0; mt < 4; mt++) {
        int row = bm + warp_m * 64 + mt * 16 + g;
#pragma unroll
        for (int nt = 0; nt < 4; nt++) {
            int col = bn + warp_n * 32 + nt * 8 + tg * 2;
            float bx = bias[col], by = bias[col + 1];
            float v00 = (acc[mt][nt][0] + bx) * oscale, v01 = (acc[mt][nt][1] + by) * oscale;
            float v10 = (acc[mt][nt][2] + bx) * oscale, v11 = (acc[mt][nt][3] + by) * oscale;
            if (fin) {
                float2 a0 = {v00, v01}, a1 = {v10, v11};
                *(float2*)&Cext[(size_t)row * EMB + col] = a0;
                *(float2*)&Cext[(size_t)(row + 8) * EMB + col] = a1;
            } else {
                __half* dst = (z == 0) ? g_qh : ((z == 1) ? g_kh : g_vh);
                *(uint32_t*)&dst[(size_t)row * EMB + col] = f2h2(v00, v01);
                *(uint32_t*)&dst[(size_t)(row + 8) * EMB + col] = f2h2(v10, v11);
            }
        }
    }
}

// ---------------------------------------------------------------------------
// HMMA banded flash attention, no-max softmax, 2-stage K/V double buffer,
// fused per-key-group dataflow. Q now has its OWN smem region so its load
// overlaps chunk 0's K/V load (commit Q first, then kv0; wait_group(1) ->
// Q ready while kv0 still in flight). One CTA per (b,h,64-q tile), 4 warps.
// smem 40KB: Q 8KB + 2 x (K 8KB + V 8KB).
// ---------------------------------------------------------------------------
__global__ __launch_bounds__(128) void attn_mma()
{
    __shared__ __align__(1024) char smem_buf[40960];
    const uint32_t sbQ = smem_u32(smem_buf);          // Q region (8KB)
    const uint32_t sb0 = sbQ + 8192;                  // K/V stages (2x16KB)

    const int tid = threadIdx.x;
    const int lane = tid & 31;
    const int wid = tid >> 5;
    const int q0 = blockIdx.x * 64;
    const int h = blockIdx.y;
    const int b = blockIdx.z;

    const int lr = lane & 15;
    const int lh = lane >> 4;
    const int l7 = lane & 7;
    const int g = lane >> 2;
    const int tg = lane & 3;

    const size_t tok0 = (size_t)b * SEQ;
    const int colh = h * DHEAD;

    int klo_ = q0 - WINDOW; if (klo_ < 0) klo_ = 0;
    int khi_ = q0 + 64 + WINDOW; if (khi_ > SEQ) khi_ = SEQ;
    const int nch = (khi_ - klo_) >> 6;

    auto load_kv = [&](int buf, int kc) {
        uint32_t base = sb0 + (uint32_t)buf * 16384;
#pragma unroll
        for (int i = 0; i < 4; i++) {
            int idx = tid + i * 128;
            int rr = idx >> 3, cc = idx & 7;
            uint32_t so = rr * 128 + ((cc ^ (rr & 7)) * 16);
            cp16(base + so, g_kh + (tok0 + kc + rr) * EMB + colh + cc * 8);
            cp16(base + 8192 + so, g_vh + (tok0 + kc + rr) * EMB + colh + cc * 8);
        }
        CP_COMMIT();
    };

    // ---- issue Q (group 0), then chunk-0 K/V (group 1) ----
#pragma unroll
    for (int i = 0; i < 4; i++) {
        int idx = tid + i * 128;
        int rr = idx >> 3, cc = idx & 7;
        cp16(sbQ + rr * 128 + ((cc ^ (rr & 7)) * 16),
             g_qh + (tok0 + q0 + rr) * EMB + colh + cc * 8);
    }
    CP_COMMIT();
    load_kv(0, klo_);

    // wait for Q only (kv0 still in flight), extract fragments
    CP_WAIT(1);
    __syncthreads();

    uint32_t qh[4][4];
#pragma unroll
    for (int kk = 0; kk < 4; kk++) {
        uint32_t ch = (uint32_t)(((kk * 2) | lh) ^ l7) * 16;
        uint32_t off = (uint32_t)(wid * 16 + lr) * 128 + ch;
        ldm_x4(qh[kk][0], qh[kk][1], qh[kk][2], qh[kk][3], sbQ + off);
    }
    // no barrier: Q region is never reused

    float oacc[8][4];
#pragma unroll
    for (int j = 0; j < 8; j++)
#pragma unroll
        for (int c = 0; c < 4; c++) oacc[j][c] = 0.f;

    float l0 = 0.f, l8 = 0.f;

    const int qg0 = q0 + wid * 16 + g;
    const int qg8 = qg0 + 8;

    // fused per-group chunk body; plo/phi/typ constant-fold in the fast arm
    auto chunk_body = [&](int kc, uint32_t bK, uint32_t bV,
                          int plo, int phi, int typ) {
#pragma unroll
        for (int t = 0; t < 4; t++) {
            if (t < plo || t > phi) continue;    // warp-uniform skip (exact)

            // ---- S for this 16-key group (j = 2t, 2t+1) ----
            float s0[4] = {0.f, 0.f, 0.f, 0.f};
            float s1[4] = {0.f, 0.f, 0.f, 0.f};
#pragma unroll
            for (int kk = 0; kk < 4; kk++) {
                uint32_t ch = (uint32_t)(((kk * 2) | lh) ^ l7) * 16;
                uint32_t off = (uint32_t)(t * 16 + lr) * 128 + ch;
                uint32_t r0, r1, r2, r3;
                ldm_x4(r0, r1, r2, r3, bK + off);
                uint32_t kb0[2] = {r0, r2}, kb1[2] = {r1, r3};
                mma_f16(s0, qh[kk], kb0);
                mma_f16(s1, qh[kk], kb1);
            }

            // ---- mask (boundary chunks only) ----
            if (typ) {
                int kg0 = kc + t * 16 + tg * 2;   // keys of j=2t
                int kg1 = kg0 + 8;                // keys of j=2t+1
                if (abs(qg0 - kg0) > WINDOW)       s0[0] = -1e30f;
                if (abs(qg0 - (kg0 + 1)) > WINDOW) s0[1] = -1e30f;
                if (abs(qg8 - kg0) > WINDOW)       s0[2] = -1e30f;
                if (abs(qg8 - (kg0 + 1)) > WINDOW) s0[3] = -1e30f;
                if (abs(qg0 - kg1) > WINDOW)       s1[0] = -1e30f;
                if (abs(qg0 - (kg1 + 1)) > WINDOW) s1[1] = -1e30f;
                if (abs(qg8 - kg1) > WINDOW)       s1[2] = -1e30f;
                if (abs(qg8 - (kg1 + 1)) > WINDOW) s1[3] = -1e30f;
            }

            // ---- exp2 (no max subtraction: logits bounded), pack, l ----
            float p00 = ex2f(s0[0]), p01 = ex2f(s0[1]);
            float p02 = ex2f(s0[2]), p03 = ex2f(s0[3]);
            float p10 = ex2f(s1[0]), p11 = ex2f(s1[1]);
            float p12 = ex2f(s1[2]), p13 = ex2f(s1[3]);
            l0 += p00 + p01 + p10 + p11;
            l8 += p02 + p03 + p12 + p13;
            uint32_t pa[4] = {f2h2(p00, p01), f2h2(p02, p03),
                              f2h2(p10, p11), f2h2(p12, p13)};

            // ---- O += P V for this group ----
            int row = t * 16 + lr;
            uint32_t rbase = bV + (uint32_t)row * 128;
            uint32_t rsw = (uint32_t)(row & 7);
#pragma unroll
            for (int pp = 0; pp < 4; pp++) {
                uint32_t d = (uint32_t)(pp * 2) + (uint32_t)lh;
                uint32_t r0, r1, r2, r3;
                ldm_x4_t(r0, r1, r2, r3, rbase + ((d ^ rsw) * 16));
                uint32_t vb0[2] = {r0, r1}, vb1[2] = {r2, r3};
                mma_f16(oacc[pp * 2], pa, vb0);
                mma_f16(oacc[pp * 2 + 1], pa, vb1);
            }
        }
    };

    for (int c = 0; c < nch; c++) {
        const int kc = klo_ + c * 64;
        const int buf = c & 1;
        const int typ = (kc == q0 - 128) ? 1 : ((kc == q0 + 128) ? 2 : 0);

        CP_WAIT(0);
        __syncthreads();
        if (c + 1 < nch) load_kv(buf ^ 1, kc + 64);

        const uint32_t bK = sb0 + (uint32_t)buf * 16384;
        const uint32_t bV = bK + 8192;

        if (typ == 0) {
            chunk_body(kc, bK, bV, 0, 3, 0);          // fast interior path
        } else {
            const int plo = (typ == 1) ? wid : 0;
            const int phi = (typ == 2) ? wid : 3;
            chunk_body(kc, bK, bV, plo, phi, typ);    // boundary path
        }
    }

    // ---- single deferred l reduction across the 4 lanes of each row ----
    l0 += __shfl_xor_sync(0xffffffffu, l0, 1);
    l0 += __shfl_xor_sync(0xffffffffu, l0, 2);
    l8 += __shfl_xor_sync(0xffffffffu, l8, 1);
    l8 += __shfl_xor_sync(0xffffffffu, l8, 2);

    // ---- epilogue: normalize, store plain fp16 ----
    float il0 = 1.f / l0, il8 = 1.f / l8;
    size_t r0base = (tok0 + qg0) * EMB + colh;
    size_t r8base = (tok0 + qg8) * EMB + colh;
#pragma unroll
    for (int j = 0; j < 8; j++) {
        int col = j * 8 + tg * 2;
        *(uint32_t*)&g_oh[r0base + col] = f2h2(oacc[j][0] * il0, oacc[j][1] * il0);
        *(uint32_t*)&g_oh[r8base + col] = f2h2(oacc[j][2] * il8, oacc[j][3] * il8);
    }
}

// ---------------------------------------------------------------------------
extern "C" void kernel_launch(void* const* d_in, const int* in_sizes, int n_in,
                              void* d_out, int out_size)
{
    const float* x  = (const float*)d_in[0];
    const float* Wq = (const float*)d_in[1];
    const float* bq = (const float*)d_in[2];
    const float* Wk = (const float*)d_in[3];
    const float* bk = (const float*)d_in[4];
    const float* Wv = (const float*)d_in[5];
    const float* bv = (const float*)d_in[6];
    const float* Wo = (const float*)d_in[7];
    const float* bo = (const float*)d_in[8];
    float* out = (float*)d_out;

    cudaFuncSetAttribute(gemm_mma, cudaFuncAttributeMaxDynamicSharedMemorySize, GEMM_SMEM);

    conv_all<<<(CONV_QTR + 255) / 256, 256>>>(x, Wq, Wk, Wv, Wo);

    gemm_mma<<<dim3(MTOT / 128, EMB / 128, 3), 256, GEMM_SMEM>>>(bq, bk, bv, nullptr, 0);

    attn_mma<<<dim3(SEQ / 64, NHEAD, BATCH), 128>>>();

    gemm_mma<<<dim3(MTOT / 128, EMB / 128, 1), 256, GEMM_SMEM>>>(bo, nullptr, nullptr, out, 1);
}